// round 8
// baseline (speedup 1.0000x reference)
#include <cuda_runtime.h>
#include <cuda_bf16.h>

// Problem shape (fixed by the dataset): B=64 segments, L=2048 tokens each,
// N=131072 tokens, D=512 features. Output = [B*D] means ++ [N] attn weights.
#define SEG_B   64
#define FEAT_D  512
#define D4      (FEAT_D / 4)     // 128 float4 lanes
#define SPLIT   64               // chunks per segment (32 rows each @ L=2048)
#define NCHUNK  (SEG_B * SPLIT)  // 4096 work items
#define TPB     128              // one thread per float4 column lane
#define GRID    2048             // persistent CTAs; fully resident (<=16/SM*148)

// Partial sums: [B][SPLIT][D] floats = 8 MB scratch (L2-resident).
__device__ float g_partials[SEG_B * SPLIT * FEAT_D];
// Work-stealing ticket + per-segment completion + CTA-exit counter.
// All zero-initialized; each is reset in-kernel so graph replays are clean.
__device__ unsigned int g_ticket;
__device__ unsigned int g_done[SEG_B];
__device__ unsigned int g_exit;

// ---------------------------------------------------------------------------
// lengths may be int32 (JAX x64 disabled) or int64 (as declared). Detect by
// checking whether the int32 interpretation sums to the total token count.
// ---------------------------------------------------------------------------
__device__ __forceinline__ bool lengths_are_i64(const void* lengths, long long n_total)
{
    const int* p32 = (const int*)lengths;
    long long s = 0;
    #pragma unroll 8
    for (int i = 0; i < SEG_B; ++i) s += p32[i];
    return s != n_total;
}

__device__ __forceinline__ long long len_at(const void* lengths, int i, bool is64)
{
    return is64 ? ((const long long*)lengths)[i]
                : (long long)((const int*)lengths)[i];
}

__device__ __forceinline__ float4 ld_stream(const float4* p)
{
    return __ldcs(p);   // evict-first: read-once stream, keep scratch in L2
}

// ---------------------------------------------------------------------------
// Persistent fused kernel with dynamic work-stealing.
// Work item w -> (segment b = w/SPLIT, chunk c = w%SPLIT): accumulate that
// row-chunk into registers, store partial, write attn weights for its rows.
// Last chunk to finish for a segment reduces the SPLIT partials (fixed order
// -> deterministic) and writes the [D] mean. Last CTA to exit resets counters.
// ---------------------------------------------------------------------------
__global__ void __launch_bounds__(TPB)
mean_pool_fused(const float* __restrict__ x,
                const void* __restrict__ lengths,
                float* __restrict__ out,
                float* __restrict__ attn,
                long long n_total)
{
    const int t = threadIdx.x;

    __shared__ unsigned int s_w;
    __shared__ long long    s_pref[SEG_B];   // exclusive prefix of lengths
    __shared__ int          s_lens[SEG_B];
    __shared__ bool         s_is64;
    __shared__ bool         s_last;

    // Grab the first ticket immediately (narrows any reset race window; all
    // CTAs are resident from launch since GRID <= resident capacity).
    if (t == 0) {
        s_w = atomicAdd(&g_ticket, 1u);
        s_is64 = lengths_are_i64(lengths, n_total);
    }
    __syncthreads();
    const bool is64 = s_is64;

    // Parallel exclusive prefix scan of the 64 lengths (2-warp shfl scan).
    if (t < SEG_B) {
        long long li = len_at(lengths, t, is64);
        long long v  = li;
        const unsigned lane = t & 31;
        #pragma unroll
        for (int o = 1; o < 32; o <<= 1) {
            long long u = __shfl_up_sync(0xffffffffu, v, o);
            if (lane >= o) v += u;
        }
        s_pref[t] = v;            // inclusive within warp
        s_lens[t] = (int)li;
    }
    __syncthreads();
    const long long w0tot = s_pref[31];
    __syncthreads();
    if (t < SEG_B) {
        long long incl = s_pref[t] + ((t >= 32) ? w0tot : 0);
        s_pref[t] = incl - (long long)s_lens[t];   // exclusive prefix
    }
    __syncthreads();

    unsigned int w = s_w;
    while (w < NCHUNK) {
        const int b = (int)(w >> 6);          // w / SPLIT
        const int c = (int)(w & (SPLIT - 1)); // w % SPLIT

        const long long seg_start = s_pref[b];
        const int len        = s_lens[b];
        const int chunk_rows = (len + SPLIT - 1) / SPLIT;
        const int r0         = c * chunk_rows;
        const int rows       = max(min(chunk_rows, len - r0), 0);

        const float4* __restrict__ xr =
            reinterpret_cast<const float4*>(x) + (seg_start + r0) * (long long)D4;

        float4 acc = make_float4(0.f, 0.f, 0.f, 0.f);
        int r = 0;
        for (; r + 4 <= rows; r += 4) {
            float4 a0 = ld_stream(&xr[(long long)(r + 0) * D4 + t]);
            float4 a1 = ld_stream(&xr[(long long)(r + 1) * D4 + t]);
            float4 a2 = ld_stream(&xr[(long long)(r + 2) * D4 + t]);
            float4 a3 = ld_stream(&xr[(long long)(r + 3) * D4 + t]);
            acc.x += (a0.x + a1.x) + (a2.x + a3.x);
            acc.y += (a0.y + a1.y) + (a2.y + a3.y);
            acc.z += (a0.z + a1.z) + (a2.z + a3.z);
            acc.w += (a0.w + a1.w) + (a2.w + a3.w);
        }
        for (; r < rows; ++r) {
            float4 a = ld_stream(&xr[(long long)r * D4 + t]);
            acc.x += a.x; acc.y += a.y; acc.z += a.z; acc.w += a.w;
        }

        reinterpret_cast<float4*>(g_partials)[(b * SPLIT + c) * D4 + t] = acc;

        const float inv = 1.0f / (float)len;
        for (int rr = t; rr < rows; rr += TPB)
            attn[seg_start + r0 + rr] = inv;

        // ---- last-chunk-done reduction for this segment ----
        __threadfence();                      // release: partial visible
        if (t == 0) {
            unsigned int prev = atomicAdd(&g_done[b], 1u);
            s_last = (prev == SPLIT - 1);
        }
        __syncthreads();

        if (s_last) {
            __threadfence();                  // acquire: see all partials
            const float4* __restrict__ base =
                reinterpret_cast<const float4*>(g_partials) + b * SPLIT * D4;
            float4 sum = make_float4(0.f, 0.f, 0.f, 0.f);
            #pragma unroll 8
            for (int cc = 0; cc < SPLIT; ++cc) {
                float4 a = base[cc * D4 + t];
                sum.x += a.x; sum.y += a.y; sum.z += a.z; sum.w += a.w;
            }
            sum.x *= inv; sum.y *= inv; sum.z *= inv; sum.w *= inv;
            reinterpret_cast<float4*>(out)[b * D4 + t] = sum;
            if (t == 0) g_done[b] = 0;        // reset for next replay
        }
        __syncthreads();                      // protect s_last / s_w reuse

        if (t == 0) s_w = atomicAdd(&g_ticket, 1u);
        __syncthreads();
        w = s_w;
    }

    // ---- exit protocol: last CTA out resets the ticket for the next replay.
    // Every CTA has drawn its exit ticket (w >= NCHUNK) before this point, so
    // no further atomicAdds on g_ticket can happen this launch.
    if (t == 0) {
        __threadfence();
        unsigned int prev = atomicAdd(&g_exit, 1u);
        if (prev == (unsigned int)(gridDim.x * gridDim.y) - 1u) {
            g_ticket = 0;
            g_exit   = 0;
            __threadfence();
        }
    }
}

extern "C" void kernel_launch(void* const* d_in, const int* in_sizes, int n_in,
                              void* d_out, int out_size)
{
    const float* x       = (const float*)d_in[0];
    const void*  lengths = d_in[1];

    const long long n_total = (long long)in_sizes[0] / FEAT_D;

    float* out  = (float*)d_out;                 // [B, D] means first
    float* attn = out + SEG_B * FEAT_D;          // [N] attention weights

    mean_pool_fused<<<GRID, TPB>>>(x, lengths, out, attn, n_total);
}

// round 9
// speedup vs baseline: 1.0437x; 1.0437x over previous
#include <cuda_runtime.h>
#include <cuda_bf16.h>

// Problem shape (fixed by the dataset): B=64 segments, L=2048 tokens each,
// N=131072 tokens, D=512 features. Output = [B*D] means ++ [N] attn weights.
#define SEG_B    64
#define FEAT_D   512
#define D4       (FEAT_D / 4)    // 128 float4 per row
#define GSLABS   32              // column-slabs per segment (16 floats each)
#define SLAB_F4  4               // float4 lanes per slab (16 floats = 64B)
#define TPB      128             // 32 row-ways x 4 lanes

// ---------------------------------------------------------------------------
// lengths may be int32 (JAX x64 disabled) or int64 (as declared). Detect by
// checking whether the int32 interpretation sums to the total token count.
// ---------------------------------------------------------------------------
__device__ __forceinline__ bool lengths_are_i64(const void* lengths, long long n_total)
{
    const int* p32 = (const int*)lengths;
    long long s = 0;
    #pragma unroll 8
    for (int i = 0; i < SEG_B; ++i) s += p32[i];
    return s != n_total;
}

__device__ __forceinline__ long long len_at(const void* lengths, int i, bool is64)
{
    return is64 ? ((const long long*)lengths)[i]
                : (long long)((const int*)lengths)[i];
}

// ---------------------------------------------------------------------------
// One kernel, no scratch, no atomics. Block (g, b) owns ALL rows of segment b
// for a 16-float column slab [g*16, g*16+16). Threads: 32 row-ways x 4 lanes.
// Each thread accumulates len/32 rows in a register float4; a tiny smem tree
// folds the 32 row-ways; 4 threads write the slab of the [B,D] mean directly.
// attn weights: block g writes its 1/32 share of the segment's rows.
// Fixed summation order -> deterministic.
// ---------------------------------------------------------------------------
__global__ void __launch_bounds__(TPB)
mean_pool_slab(const float* __restrict__ x,
               const void* __restrict__ lengths,
               float* __restrict__ out,
               float* __restrict__ attn,
               long long n_total)
{
    const int g = blockIdx.x;               // column slab 0..31
    const int b = blockIdx.y;               // segment 0..63
    const int t = threadIdx.x;
    const int row_way = t >> 2;             // 0..31
    const int lane    = t & 3;              // 0..3 (float4 within slab)

    __shared__ long long s_start;
    __shared__ int       s_len;
    if (t == 0) {
        const bool is64 = lengths_are_i64(lengths, n_total);
        long long st = 0;
        int myl = 0;
        for (int i = 0; i < SEG_B; ++i) {
            long long li = len_at(lengths, i, is64);
            if (i < b) st += li;
            if (i == b) myl = (int)li;
        }
        s_start = st;
        s_len   = myl;
    }
    __syncthreads();

    const long long seg_start = s_start;
    const int len = s_len;

    // float4 column index for this thread within a row
    const int col4 = g * SLAB_F4 + lane;
    const float4* __restrict__ xr =
        reinterpret_cast<const float4*>(x) + seg_start * (long long)D4 + col4;

    float4 acc = make_float4(0.f, 0.f, 0.f, 0.f);

    // rows r = row_way, row_way+32, ... ; unroll 4 -> 4 outstanding LDG.128
    int r = row_way;
    const long long stride = 32LL * D4;
    const float4* p = xr + (long long)row_way * D4;
    for (; r + 96 < len; r += 128, p += 4 * stride) {
        float4 a0 = p[0 * stride];
        float4 a1 = p[1 * stride];
        float4 a2 = p[2 * stride];
        float4 a3 = p[3 * stride];
        acc.x += (a0.x + a1.x) + (a2.x + a3.x);
        acc.y += (a0.y + a1.y) + (a2.y + a3.y);
        acc.z += (a0.z + a1.z) + (a2.z + a3.z);
        acc.w += (a0.w + a1.w) + (a2.w + a3.w);
    }
    for (; r < len; r += 32, p += stride) {
        float4 a = p[0];
        acc.x += a.x; acc.y += a.y; acc.z += a.z; acc.w += a.w;
    }

    // attn weights: block g writes rows [g*chunk, min((g+1)*chunk, len))
    const float inv = 1.0f / (float)len;
    {
        const int chunk = (len + GSLABS - 1) / GSLABS;
        const int a0 = g * chunk;
        const int a1 = min(a0 + chunk, len);
        for (int rr = a0 + t; rr < a1; rr += TPB)
            attn[seg_start + rr] = inv;
    }

    // Fold the 32 row-ways per lane: smem tree (fixed order, deterministic).
    __shared__ float4 s_red[TPB];
    s_red[t] = acc;
    __syncthreads();
    #pragma unroll
    for (int off = 64; off >= 4; off >>= 1) {
        if (t < off) {
            float4 o = s_red[t + off];
            float4 m = s_red[t];
            m.x += o.x; m.y += o.y; m.z += o.z; m.w += o.w;
            s_red[t] = m;
        }
        __syncthreads();
    }

    if (t < SLAB_F4) {
        float4 m = s_red[t];
        m.x *= inv; m.y *= inv; m.z *= inv; m.w *= inv;
        reinterpret_cast<float4*>(out)[b * D4 + g * SLAB_F4 + t] = m;
    }
}

extern "C" void kernel_launch(void* const* d_in, const int* in_sizes, int n_in,
                              void* d_out, int out_size)
{
    const float* x       = (const float*)d_in[0];
    const void*  lengths = d_in[1];

    const long long n_total = (long long)in_sizes[0] / FEAT_D;

    float* out  = (float*)d_out;                 // [B, D] means first
    float* attn = out + SEG_B * FEAT_D;          // [N] attention weights

    dim3 grid(GSLABS, SEG_B);                    // 32 x 64 = 2048 CTAs, 1 wave
    mean_pool_slab<<<grid, TPB>>>(x, lengths, out, attn, n_total);
}

// round 10
// speedup vs baseline: 1.0727x; 1.0277x over previous
#include <cuda_runtime.h>
#include <cuda_bf16.h>

// Problem shape (fixed by the dataset): B=64 segments, L=2048 tokens each,
// N=131072 tokens, D=512 features. Output = [B*D] means ++ [N] attn weights.
#define SEG_B    64
#define FEAT_D   512
#define D4       (FEAT_D / 4)    // 128 float4 per row
#define GSLABS   16              // column-slabs per segment (32 floats = 128B)
#define SLAB_F4  8               // float4 lanes per slab
#define TPB      256             // 32 row-ways x 8 lanes

// ---------------------------------------------------------------------------
// lengths may be int32 (JAX x64 disabled) or int64 (as declared). Detect by
// checking whether the int32 interpretation sums to the total token count.
// ---------------------------------------------------------------------------
__device__ __forceinline__ bool lengths_are_i64(const void* lengths, long long n_total)
{
    const int* p32 = (const int*)lengths;
    long long s = 0;
    #pragma unroll 8
    for (int i = 0; i < SEG_B; ++i) s += p32[i];
    return s != n_total;
}

__device__ __forceinline__ long long len_at(const void* lengths, int i, bool is64)
{
    return is64 ? ((const long long*)lengths)[i]
                : (long long)((const int*)lengths)[i];
}

// ---------------------------------------------------------------------------
// One kernel, no scratch, no atomics, no fences. Block (g, b) owns ALL rows
// of segment b for a 32-float (128-byte, full-line) column slab.
// Threads: 32 row-ways x 8 float4-lanes; a warp covers 4 rows x 128B
// contiguous -> 4 full cache lines per LDG.128 (optimal wavefront count).
// Each thread accumulates len/32 rows in a register float4; one smem tree
// folds the 32 row-ways; 8 threads write the slab of the [B,D] mean.
// attn weights: block g writes its 1/16 share of the segment's rows.
// Fixed summation order -> deterministic.
// ---------------------------------------------------------------------------
__global__ void __launch_bounds__(TPB)
mean_pool_slab(const float* __restrict__ x,
               const void* __restrict__ lengths,
               float* __restrict__ out,
               float* __restrict__ attn,
               long long n_total)
{
    const int g = blockIdx.x;               // column slab 0..15
    const int b = blockIdx.y;               // segment 0..63
    const int t = threadIdx.x;
    const int row_way = t >> 3;             // 0..31
    const int lane    = t & 7;              // 0..7 (float4 within slab)

    __shared__ long long s_start;
    __shared__ int       s_len;
    if (t == 0) {
        const bool is64 = lengths_are_i64(lengths, n_total);
        long long st = 0;
        int myl = 0;
        for (int i = 0; i < SEG_B; ++i) {
            long long li = len_at(lengths, i, is64);
            if (i < b) st += li;
            if (i == b) myl = (int)li;
        }
        s_start = st;
        s_len   = myl;
    }
    __syncthreads();

    const long long seg_start = s_start;
    const int len = s_len;

    // float4 column index for this thread within a row
    const int col4 = g * SLAB_F4 + lane;

    float4 acc = make_float4(0.f, 0.f, 0.f, 0.f);

    // rows r = row_way, row_way+32, ... ; unroll 4 -> 4 outstanding LDG.128
    const long long stride = 32LL * D4;
    const float4* p = reinterpret_cast<const float4*>(x)
                      + (seg_start + row_way) * (long long)D4 + col4;
    int r = row_way;
    for (; r + 96 < len; r += 128, p += 4 * stride) {
        float4 a0 = p[0 * stride];
        float4 a1 = p[1 * stride];
        float4 a2 = p[2 * stride];
        float4 a3 = p[3 * stride];
        acc.x += (a0.x + a1.x) + (a2.x + a3.x);
        acc.y += (a0.y + a1.y) + (a2.y + a3.y);
        acc.z += (a0.z + a1.z) + (a2.z + a3.z);
        acc.w += (a0.w + a1.w) + (a2.w + a3.w);
    }
    for (; r < len; r += 32, p += stride) {
        float4 a = p[0];
        acc.x += a.x; acc.y += a.y; acc.z += a.z; acc.w += a.w;
    }

    // attn weights: block g writes rows [g*chunk, min((g+1)*chunk, len))
    const float inv = 1.0f / (float)len;
    {
        const int chunk = (len + GSLABS - 1) / GSLABS;
        const int a0 = g * chunk;
        const int a1 = min(a0 + chunk, len);
        for (int rr = a0 + t; rr < a1; rr += TPB)
            attn[seg_start + rr] = inv;
    }

    // Fold the 32 row-ways per lane: smem tree (fixed order, deterministic).
    __shared__ float4 s_red[TPB];
    s_red[t] = acc;
    __syncthreads();
    #pragma unroll
    for (int off = TPB / 2; off >= SLAB_F4; off >>= 1) {
        if (t < off) {
            float4 o = s_red[t + off];
            float4 m = s_red[t];
            m.x += o.x; m.y += o.y; m.z += o.z; m.w += o.w;
            s_red[t] = m;
        }
        __syncthreads();
    }

    if (t < SLAB_F4) {
        float4 m = s_red[t];
        m.x *= inv; m.y *= inv; m.z *= inv; m.w *= inv;
        reinterpret_cast<float4*>(out)[b * D4 + g * SLAB_F4 + t] = m;
    }
}

extern "C" void kernel_launch(void* const* d_in, const int* in_sizes, int n_in,
                              void* d_out, int out_size)
{
    const float* x       = (const float*)d_in[0];
    const void*  lengths = d_in[1];

    const long long n_total = (long long)in_sizes[0] / FEAT_D;

    float* out  = (float*)d_out;                 // [B, D] means first
    float* attn = out + SEG_B * FEAT_D;          // [N] attention weights

    dim3 grid(GSLABS, SEG_B);                    // 16 x 64 = 1024 CTAs, 1 wave
    mean_pool_slab<<<grid, TPB>>>(x, lengths, out, attn, n_total);
}

// round 11
// speedup vs baseline: 1.0780x; 1.0050x over previous
#include <cuda_runtime.h>
#include <cuda_bf16.h>

// Problem shape (fixed by the dataset): B=64 segments, L=2048 tokens each,
// N=131072 tokens, D=512 features. Output = [B*D] means ++ [N] attn weights.
#define SEG_B    64
#define FEAT_D   512
#define D4       (FEAT_D / 4)    // 128 float4 per row
#define GSLABS   16              // column-slabs per segment (32 floats = 128B)
#define SLAB_F4  8               // float4 lanes per slab
#define TPB      256             // 32 row-ways x 8 lanes

// ---------------------------------------------------------------------------
// lengths may be int32 (JAX x64 disabled) or int64 (as declared). Detect by
// checking whether the int32 interpretation sums to the total token count.
// ---------------------------------------------------------------------------
__device__ __forceinline__ bool lengths_are_i64(const void* lengths, long long n_total)
{
    const int* p32 = (const int*)lengths;
    long long s = 0;
    #pragma unroll 8
    for (int i = 0; i < SEG_B; ++i) s += p32[i];
    return s != n_total;
}

__device__ __forceinline__ long long len_at(const void* lengths, int i, bool is64)
{
    return is64 ? ((const long long*)lengths)[i]
                : (long long)((const int*)lengths)[i];
}

// ---------------------------------------------------------------------------
// One kernel, no scratch, no atomics, no fences. Block (g, b) owns ALL rows
// of segment b for a 32-float (128-byte, full-line) column slab.
// Threads: 32 row-ways x 8 float4-lanes; a warp covers 4 rows x 128B
// contiguous -> 4 full cache lines per LDG.128 (optimal wavefront count).
// Each thread accumulates len/32 rows in a register float4; one smem tree
// folds the 32 row-ways; 8 threads write the slab of the [B,D] mean.
// attn weights: block g writes its 1/16 share of the segment's rows.
// Fixed summation order -> deterministic.
// ---------------------------------------------------------------------------
__global__ void __launch_bounds__(TPB)
mean_pool_slab(const float* __restrict__ x,
               const void* __restrict__ lengths,
               float* __restrict__ out,
               float* __restrict__ attn,
               long long n_total)
{
    const int g = blockIdx.x;               // column slab 0..15
    const int b = blockIdx.y;               // segment 0..63
    const int t = threadIdx.x;
    const int row_way = t >> 3;             // 0..31
    const int lane    = t & 7;              // 0..7 (float4 within slab)

    __shared__ long long s_start;
    __shared__ int       s_len;
    if (t == 0) {
        const bool is64 = lengths_are_i64(lengths, n_total);
        long long st = 0;
        int myl = 0;
        for (int i = 0; i < SEG_B; ++i) {
            long long li = len_at(lengths, i, is64);
            if (i < b) st += li;
            if (i == b) myl = (int)li;
        }
        s_start = st;
        s_len   = myl;
    }
    __syncthreads();

    const long long seg_start = s_start;
    const int len = s_len;

    // float4 column index for this thread within a row
    const int col4 = g * SLAB_F4 + lane;

    float4 acc = make_float4(0.f, 0.f, 0.f, 0.f);

    // rows r = row_way, row_way+32, ... ; unroll 4 -> 4 outstanding LDG.128
    const long long stride = 32LL * D4;
    const float4* p = reinterpret_cast<const float4*>(x)
                      + (seg_start + row_way) * (long long)D4 + col4;
    int r = row_way;
    for (; r + 96 < len; r += 128, p += 4 * stride) {
        float4 a0 = p[0 * stride];
        float4 a1 = p[1 * stride];
        float4 a2 = p[2 * stride];
        float4 a3 = p[3 * stride];
        acc.x += (a0.x + a1.x) + (a2.x + a3.x);
        acc.y += (a0.y + a1.y) + (a2.y + a3.y);
        acc.z += (a0.z + a1.z) + (a2.z + a3.z);
        acc.w += (a0.w + a1.w) + (a2.w + a3.w);
    }
    for (; r < len; r += 32, p += stride) {
        float4 a = p[0];
        acc.x += a.x; acc.y += a.y; acc.z += a.z; acc.w += a.w;
    }

    // attn weights: block g writes rows [g*chunk, min((g+1)*chunk, len))
    const float inv = 1.0f / (float)len;
    {
        const int chunk = (len + GSLABS - 1) / GSLABS;
        const int a0 = g * chunk;
        const int a1 = min(a0 + chunk, len);
        for (int rr = a0 + t; rr < a1; rr += TPB)
            attn[seg_start + rr] = inv;
    }

    // Fold the 32 row-ways per lane: smem tree (fixed order, deterministic).
    __shared__ float4 s_red[TPB];
    s_red[t] = acc;
    __syncthreads();
    #pragma unroll
    for (int off = TPB / 2; off >= SLAB_F4; off >>= 1) {
        if (t < off) {
            float4 o = s_red[t + off];
            float4 m = s_red[t];
            m.x += o.x; m.y += o.y; m.z += o.z; m.w += o.w;
            s_red[t] = m;
        }
        __syncthreads();
    }

    if (t < SLAB_F4) {
        float4 m = s_red[t];
        m.x *= inv; m.y *= inv; m.z *= inv; m.w *= inv;
        reinterpret_cast<float4*>(out)[b * D4 + g * SLAB_F4 + t] = m;
    }
}

extern "C" void kernel_launch(void* const* d_in, const int* in_sizes, int n_in,
                              void* d_out, int out_size)
{
    const float* x       = (const float*)d_in[0];
    const void*  lengths = d_in[1];

    const long long n_total = (long long)in_sizes[0] / FEAT_D;

    float* out  = (float*)d_out;                 // [B, D] means first
    float* attn = out + SEG_B * FEAT_D;          // [N] attention weights

    dim3 grid(GSLABS, SEG_B);                    // 16 x 64 = 1024 CTAs, 1 wave
    mean_pool_slab<<<grid, TPB>>>(x, lengths, out, attn, n_total);
}

// round 12
// speedup vs baseline: 1.1181x; 1.0372x over previous
#include <cuda_runtime.h>
#include <cuda_bf16.h>

// Problem shape (fixed by the dataset): B=64 segments, L=2048 tokens each,
// N=131072 tokens, D=512 features. Output = [B*D] means ++ [N] attn weights.
#define SEG_B   64
#define FEAT_D  512
#define D4      (FEAT_D / 4)     // 128 float4 lanes
#define SPLIT   32               // row-chunks per segment
#define TPB     128              // one thread per float4 column lane

// Phase-1 partial sums: [B][SPLIT][D] floats = 4 MB scratch (L2-resident).
__device__ float g_partials[SEG_B * SPLIT * FEAT_D];
// Per-segment completion counters; reducer resets them each launch.
__device__ unsigned int g_done[SEG_B];

// ---------------------------------------------------------------------------
// lengths may be int32 (JAX x64 disabled) or int64 (as declared). Detect by
// checking whether the int32 interpretation sums to the total token count.
// ---------------------------------------------------------------------------
__device__ __forceinline__ bool lengths_are_i64(const void* lengths, long long n_total)
{
    const int* p32 = (const int*)lengths;
    long long s = 0;
    #pragma unroll 8
    for (int i = 0; i < SEG_B; ++i) s += p32[i];
    return s != n_total;
}

__device__ __forceinline__ long long len_at(const void* lengths, int i, bool is64)
{
    return is64 ? ((const long long*)lengths)[i]
                : (long long)((const int*)lengths)[i];
}

// Streaming load: evict-first in L2 so the 256 MB x-stream does NOT displace
// the 4 MB partials; the tail reducers then hit L2 instead of DRAM.
__device__ __forceinline__ float4 ld_stream(const float4* p) { return __ldcs(p); }

// ---------------------------------------------------------------------------
// Single fused kernel: block = (segment b, row-chunk c), fully contiguous
// 64-row x 512-col stream per block (the proven fastest access pattern).
//  1) accumulate chunk into per-thread float4 registers
//  2) __stcg the partial, fence, bump segment counter
//  3) last block for segment b reduces the 32 partials (L2-hot now) and
//     writes the [D] mean -- fixed order, deterministic
//  4) attn writes happen AFTER the fence/atomic so the fence need not drain
//     them (they require no ordering).
// ---------------------------------------------------------------------------
__global__ void __launch_bounds__(TPB)
mean_pool_fused(const float* __restrict__ x,
                const void* __restrict__ lengths,
                float* __restrict__ out,
                float* __restrict__ attn,
                long long n_total)
{
    const int b     = blockIdx.y;
    const int chunk = blockIdx.x;
    const int t     = threadIdx.x;           // float4 lane 0..127

    __shared__ long long s_start;
    __shared__ int       s_len;
    if (t == 0) {
        const bool is64 = lengths_are_i64(lengths, n_total);
        long long st = 0;
        int myl = 0;
        for (int i = 0; i < SEG_B; ++i) {
            long long li = len_at(lengths, i, is64);
            if (i < b) st += li;
            if (i == b) myl = (int)li;
        }
        s_start = st;
        s_len   = myl;
    }
    __syncthreads();

    const long long seg_start = s_start;
    const int len        = s_len;
    const int chunk_rows = (len + SPLIT - 1) / SPLIT;
    const int r0         = chunk * chunk_rows;
    const int rows       = max(min(chunk_rows, len - r0), 0);

    const float4* __restrict__ xr =
        reinterpret_cast<const float4*>(x) + (seg_start + r0) * (long long)D4;

    float4 acc = make_float4(0.f, 0.f, 0.f, 0.f);

    int r = 0;
    for (; r + 4 <= rows; r += 4) {
        float4 a0 = ld_stream(&xr[(long long)(r + 0) * D4 + t]);
        float4 a1 = ld_stream(&xr[(long long)(r + 1) * D4 + t]);
        float4 a2 = ld_stream(&xr[(long long)(r + 2) * D4 + t]);
        float4 a3 = ld_stream(&xr[(long long)(r + 3) * D4 + t]);
        acc.x += (a0.x + a1.x) + (a2.x + a3.x);
        acc.y += (a0.y + a1.y) + (a2.y + a3.y);
        acc.z += (a0.z + a1.z) + (a2.z + a3.z);
        acc.w += (a0.w + a1.w) + (a2.w + a3.w);
    }
    for (; r < rows; ++r) {
        float4 a = ld_stream(&xr[(long long)r * D4 + t]);
        acc.x += a.x; acc.y += a.y; acc.z += a.z; acc.w += a.w;
    }

    // Partial store straight to L2 (evict-normal: it WILL be re-read soon).
    __stcg(reinterpret_cast<float4*>(g_partials) + (b * SPLIT + chunk) * D4 + t,
           acc);

    // ---- last-block-done reduction for this segment ----
    __threadfence();                         // release: partial visible
    __shared__ bool s_last;
    if (t == 0) {
        unsigned int prev = atomicAdd(&g_done[b], 1u);
        s_last = (prev == SPLIT - 1);
    }
    __syncthreads();

    const float inv = 1.0f / (float)len;

    if (s_last) {
        __threadfence();                     // acquire: see all partials
        const float4* __restrict__ base =
            reinterpret_cast<const float4*>(g_partials) + b * SPLIT * D4;
        float4 sum = make_float4(0.f, 0.f, 0.f, 0.f);
        #pragma unroll
        for (int c = 0; c < SPLIT; ++c) {
            float4 a = base[c * D4 + t];
            sum.x += a.x; sum.y += a.y; sum.z += a.z; sum.w += a.w;
        }
        sum.x *= inv; sum.y *= inv; sum.z *= inv; sum.w *= inv;
        reinterpret_cast<float4*>(out)[b * D4 + t] = sum;
        if (t == 0) g_done[b] = 0;           // reset for next graph replay
    }

    // attn weights for the rows this block owns (after the fence on purpose)
    for (int rr = t; rr < rows; rr += TPB)
        attn[seg_start + r0 + rr] = inv;
}

extern "C" void kernel_launch(void* const* d_in, const int* in_sizes, int n_in,
                              void* d_out, int out_size)
{
    const float* x       = (const float*)d_in[0];
    const void*  lengths = d_in[1];

    const long long n_total = (long long)in_sizes[0] / FEAT_D;

    float* out  = (float*)d_out;                 // [B, D] means first
    float* attn = out + SEG_B * FEAT_D;          // [N] attention weights

    dim3 grid(SPLIT, SEG_B);                     // 32 x 64 = 2048 CTAs, 1 wave
    mean_pool_fused<<<grid, TPB>>>(x, lengths, out, attn, n_total);
}

// round 13
// speedup vs baseline: 1.1707x; 1.0470x over previous
#include <cuda_runtime.h>
#include <cuda_bf16.h>

// Problem shape (fixed by the dataset): B=64 segments, L=2048 tokens each,
// N=131072 tokens, D=512 features. Output = [B*D] means ++ [N] attn weights.
#define SEG_B   64
#define FEAT_D  512
#define D4      (FEAT_D / 4)     // 128 float4 lanes
#define SPLIT   32               // row-chunks per segment
#define TPB     128              // one thread per float4 column lane

// ---------------------------------------------------------------------------
// lengths may be int32 (JAX x64 disabled) or int64 (as declared). Detect by
// checking whether the int32 interpretation sums to the total token count.
// ---------------------------------------------------------------------------
__device__ __forceinline__ bool lengths_are_i64(const void* lengths, long long n_total)
{
    const int* p32 = (const int*)lengths;
    long long s = 0;
    #pragma unroll 8
    for (int i = 0; i < SEG_B; ++i) s += p32[i];
    return s != n_total;
}

__device__ __forceinline__ long long len_at(const void* lengths, int i, bool is64)
{
    return is64 ? ((const long long*)lengths)[i]
                : (long long)((const int*)lengths)[i];
}

// Streaming load: evict-first in L2 so the 256 MB x-stream does not displace
// the small L2-resident out region the atomics accumulate into.
__device__ __forceinline__ float4 ld_stream(const float4* p) { return __ldcs(p); }

// ---------------------------------------------------------------------------
// Single streaming kernel, no scratch, no fences, no counters.
// Block = (segment b, row-chunk c): accumulate its contiguous 64x512 chunk
// into per-thread float4 registers (the proven fastest access pattern),
// scale by 1/len, and atomicAdd the 4 floats into out[b] (pre-zeroed by a
// memset node). Each out element receives SPLIT spread-in-time adds ->
// negligible contention; fp ordering jitter ~1 ulp, far below 1e-3 rel_err.
// attn weights written directly.
// ---------------------------------------------------------------------------
__global__ void __launch_bounds__(TPB)
mean_pool_stream(const float* __restrict__ x,
                 const void* __restrict__ lengths,
                 float* __restrict__ out,
                 float* __restrict__ attn,
                 long long n_total)
{
    const int b     = blockIdx.y;
    const int chunk = blockIdx.x;
    const int t     = threadIdx.x;           // float4 lane 0..127

    __shared__ long long s_start;
    __shared__ int       s_len;
    if (t == 0) {
        const bool is64 = lengths_are_i64(lengths, n_total);
        long long st = 0;
        int myl = 0;
        for (int i = 0; i < SEG_B; ++i) {
            long long li = len_at(lengths, i, is64);
            if (i < b) st += li;
            if (i == b) myl = (int)li;
        }
        s_start = st;
        s_len   = myl;
    }
    __syncthreads();

    const long long seg_start = s_start;
    const int len        = s_len;
    const int chunk_rows = (len + SPLIT - 1) / SPLIT;
    const int r0         = chunk * chunk_rows;
    const int rows       = max(min(chunk_rows, len - r0), 0);

    const float4* __restrict__ xr =
        reinterpret_cast<const float4*>(x) + (seg_start + r0) * (long long)D4;

    float4 acc = make_float4(0.f, 0.f, 0.f, 0.f);

    int r = 0;
    for (; r + 4 <= rows; r += 4) {
        float4 a0 = ld_stream(&xr[(long long)(r + 0) * D4 + t]);
        float4 a1 = ld_stream(&xr[(long long)(r + 1) * D4 + t]);
        float4 a2 = ld_stream(&xr[(long long)(r + 2) * D4 + t]);
        float4 a3 = ld_stream(&xr[(long long)(r + 3) * D4 + t]);
        acc.x += (a0.x + a1.x) + (a2.x + a3.x);
        acc.y += (a0.y + a1.y) + (a2.y + a3.y);
        acc.z += (a0.z + a1.z) + (a2.z + a3.z);
        acc.w += (a0.w + a1.w) + (a2.w + a3.w);
    }
    for (; r < rows; ++r) {
        float4 a = ld_stream(&xr[(long long)r * D4 + t]);
        acc.x += a.x; acc.y += a.y; acc.z += a.z; acc.w += a.w;
    }

    // Scaled chunk-partial straight into out via fp atomics (REDG, no return).
    const float inv = 1.0f / (float)len;
    float* o = out + b * FEAT_D + t * 4;
    atomicAdd(o + 0, acc.x * inv);
    atomicAdd(o + 1, acc.y * inv);
    atomicAdd(o + 2, acc.z * inv);
    atomicAdd(o + 3, acc.w * inv);

    // attn weights for the rows this block owns
    for (int rr = t; rr < rows; rr += TPB)
        attn[seg_start + r0 + rr] = inv;
}

extern "C" void kernel_launch(void* const* d_in, const int* in_sizes, int n_in,
                              void* d_out, int out_size)
{
    const float* x       = (const float*)d_in[0];
    const void*  lengths = d_in[1];

    const long long n_total = (long long)in_sizes[0] / FEAT_D;

    float* out  = (float*)d_out;                 // [B, D] means first
    float* attn = out + SEG_B * FEAT_D;          // [N] attention weights

    // Zero only the mean region (atomics accumulate into it). Graph-legal.
    cudaMemsetAsync(out, 0, SEG_B * FEAT_D * sizeof(float), 0);

    dim3 grid(SPLIT, SEG_B);                     // 32 x 64 = 2048 CTAs, 1 wave
    mean_pool_stream<<<grid, TPB>>>(x, lengths, out, attn, n_total);
}

// round 14
// speedup vs baseline: 1.2173x; 1.0398x over previous
#include <cuda_runtime.h>
#include <cuda_bf16.h>

// Problem shape (fixed by the dataset): B=64 segments, L=2048 tokens each,
// N=131072 tokens, D=512 features. Output = [B*D] means ++ [N] attn weights.
#define SEG_B   64
#define FEAT_D  512
#define D4      (FEAT_D / 4)     // 128 float4 lanes per row
#define SPLIT   16               // row-chunks per segment (128 rows each)
#define TPB     256              // 2 row-ways x 128 float4 lanes

__device__ __forceinline__ float4 ld_stream(const float4* p) { return __ldcs(p); }

// ---------------------------------------------------------------------------
// Single streaming kernel. Block = (segment b, row-chunk c): two row-ways of
// 128 threads each accumulate a contiguous 128x512 chunk (warp = 512B over
// 4 rows = 4 full lines, MLP 4 -- the proven fastest pattern). One smem fold
// merges the two ways, then 128 threads issue 512 fp atomicAdds into the
// pre-zeroed out[b] row (order jitter ~1ulp << 1e-3 tolerance).
// Prologue: parallel dtype-detect + shfl prefix scan of lengths (~100 cyc).
// ---------------------------------------------------------------------------
__global__ void __launch_bounds__(TPB)
mean_pool_stream(const float* __restrict__ x,
                 const void* __restrict__ lengths,
                 float* __restrict__ out,
                 float* __restrict__ attn,
                 long long n_total)
{
    const int b     = blockIdx.y;
    const int chunk = blockIdx.x;
    const int t     = threadIdx.x;
    const int way   = t >> 7;               // 0..1
    const int lane  = t & 127;              // float4 lane within row

    // ---- parallel lengths prologue (warps 0-1 fully active for t<64) ----
    __shared__ long long sh_incl[SEG_B];
    __shared__ int       sh_len[SEG_B];
    __shared__ long long sh_wsum[2];

    if (t < SEG_B) {
        const int  wid  = t >> 5;           // 0 or 1
        const int  wl   = t & 31;
        // dtype detect: sum of int32 interpretation
        long long s32 = (long long)((const int*)lengths)[t];
        #pragma unroll
        for (int o = 16; o; o >>= 1)
            s32 += __shfl_xor_sync(0xffffffffu, s32, o);
        if (wl == 0) sh_wsum[wid] = s32;
    }
    __syncthreads();
    const bool is64 = (sh_wsum[0] + sh_wsum[1]) != n_total;

    if (t < SEG_B) {
        const int  wid = t >> 5;
        const int  wl  = t & 31;
        long long li = is64 ? ((const long long*)lengths)[t]
                            : (long long)((const int*)lengths)[t];
        long long v = li;
        #pragma unroll
        for (int o = 1; o < 32; o <<= 1) {
            long long u = __shfl_up_sync(0xffffffffu, v, o);
            if (wl >= o) v += u;
        }
        sh_incl[t] = v;                     // inclusive within warp
        sh_len[t]  = (int)li;
    }
    __syncthreads();
    if (t >= 32 && t < SEG_B) sh_incl[t] += sh_incl[31];
    __syncthreads();

    const int       len       = sh_len[b];
    const long long seg_start = sh_incl[b] - (long long)len;

    const int chunk_rows = (len + SPLIT - 1) / SPLIT;
    const int r0         = chunk * chunk_rows;
    const int rows       = max(min(chunk_rows, len - r0), 0);

    // ---- streaming accumulate: rows r = way, way+2, ... (stride 2 rows) ----
    const long long row2 = 2LL * D4;        // two rows in float4s
    const float4* p = reinterpret_cast<const float4*>(x)
                      + (seg_start + r0 + way) * (long long)D4 + lane;

    float4 acc = make_float4(0.f, 0.f, 0.f, 0.f);
    int r = way;
    for (; r + 6 < rows; r += 8, p += 4 * row2) {
        float4 a0 = ld_stream(&p[0 * row2]);
        float4 a1 = ld_stream(&p[1 * row2]);
        float4 a2 = ld_stream(&p[2 * row2]);
        float4 a3 = ld_stream(&p[3 * row2]);
        acc.x += (a0.x + a1.x) + (a2.x + a3.x);
        acc.y += (a0.y + a1.y) + (a2.y + a3.y);
        acc.z += (a0.z + a1.z) + (a2.z + a3.z);
        acc.w += (a0.w + a1.w) + (a2.w + a3.w);
    }
    for (; r < rows; r += 2, p += row2) {
        float4 a = ld_stream(&p[0]);
        acc.x += a.x; acc.y += a.y; acc.z += a.z; acc.w += a.w;
    }

    const float inv = 1.0f / (float)len;

    // attn weights for the rows this block owns
    for (int rr = t; rr < rows; rr += TPB)
        attn[seg_start + r0 + rr] = inv;

    // ---- fold the two row-ways, then 512 atomics into out[b] ----
    __shared__ float4 s_red[D4];
    if (way == 1) s_red[lane] = acc;
    __syncthreads();
    if (way == 0) {
        float4 o4 = s_red[lane];
        acc.x = (acc.x + o4.x) * inv;
        acc.y = (acc.y + o4.y) * inv;
        acc.z = (acc.z + o4.z) * inv;
        acc.w = (acc.w + o4.w) * inv;
        float* o = out + b * FEAT_D + lane * 4;
        atomicAdd(o + 0, acc.x);
        atomicAdd(o + 1, acc.y);
        atomicAdd(o + 2, acc.z);
        atomicAdd(o + 3, acc.w);
    }
}

extern "C" void kernel_launch(void* const* d_in, const int* in_sizes, int n_in,
                              void* d_out, int out_size)
{
    const float* x       = (const float*)d_in[0];
    const void*  lengths = d_in[1];

    const long long n_total = (long long)in_sizes[0] / FEAT_D;

    float* out  = (float*)d_out;                 // [B, D] means first
    float* attn = out + SEG_B * FEAT_D;          // [N] attention weights

    // Zero only the mean region (atomics accumulate into it). Graph-legal.
    cudaMemsetAsync(out, 0, SEG_B * FEAT_D * sizeof(float), 0);

    dim3 grid(SPLIT, SEG_B);                     // 16 x 64 = 1024 CTAs, 1 wave
    mean_pool_stream<<<grid, TPB>>>(x, lengths, out, attn, n_total);
}